// round 5
// baseline (speedup 1.0000x reference)
#include <cuda_runtime.h>
#include <cuda_bf16.h>
#include <cstdint>
#include <cstddef>

#define NROWS 4096
#define KDIM  2048
#define VDIM  50257
#define BM 128
#define BN 128
#define BK 64
#define VTILES ((VDIM + BN - 1) / BN)   /* 393 */
#define VPAD   (VTILES * BN)            /* 50304 */
#define ASTR   72                       /* halves per smem row (64 + 8 pad) */
#define NK     (KDIM / BK)              /* 32 */
#define IGNORE_IDX (-100)

// ---------------- device scratch (static: no allocations allowed) ----------------
__device__ __nv_bfloat16 g_wh[(size_t)VPAD * KDIM];     // bf16 weight hi
__device__ __nv_bfloat16 g_wl[(size_t)VPAD * KDIM];     // bf16 weight lo (residual)
__device__ __nv_bfloat16 g_xh[(size_t)NROWS * KDIM];    // bf16 x hi
__device__ __nv_bfloat16 g_xl[(size_t)NROWS * KDIM];    // bf16 x lo
__device__ float g_spart[(size_t)VTILES * NROWS];       // partial sum-exp per (vtile,row)
__device__ float g_zy[NROWS];                           // exact fp32 logit at label
__device__ float g_nll[NROWS];
__device__ float g_vld[NROWS];
__device__ int   g_y64;                                 // 1 if labels are int64, 0 if int32

// ---------------- label dtype probe ----------------
// If the buffer is int64 (little-endian, labels < 2^31), every odd int32 word
// is a zero hi-word. If it is int32, odd words are labels (virtually never all 0).
__global__ void detect_y_kernel(const int* __restrict__ y32) {
    __shared__ int any_nonzero;
    if (threadIdx.x == 0) any_nonzero = 0;
    __syncthreads();
    for (int i = threadIdx.x; i < NROWS / 2; i += blockDim.x)
        if (y32[2 * i + 1] != 0) any_nonzero = 1;
    __syncthreads();
    if (threadIdx.x == 0) g_y64 = any_nonzero ? 0 : 1;
}

__device__ __forceinline__ int load_label(const void* y, int row) {
    if (g_y64) return (int)((const long long*)y)[row];
    return ((const int*)y)[row];
}

// ---------------- fast exp: FFMA polynomial, avoids MUFU bottleneck ----------------
__device__ __forceinline__ float fast_exp(float x) {
    x = fminf(fmaxf(x, -80.f), 80.f);
    float n = rintf(x * 1.4426950408889634f);
    float r = fmaf(n, -0.693145751953125f, x);
    r = fmaf(n, -1.428606765330187e-06f, r);
    float p = 8.3333333e-3f;
    p = fmaf(p, r, 4.1666667e-2f);
    p = fmaf(p, r, 1.6666667e-1f);
    p = fmaf(p, r, 0.5f);
    p = fmaf(p, r, 1.0f);
    p = fmaf(p, r, 1.0f);
    return __int_as_float(__float_as_int(p) + (((int)n) << 23));
}

// ---------------- split conversion: v = hi + lo, both bf16 ----------------
__device__ __forceinline__ void split2(float2 v, uint32_t& hi, uint32_t& lo) {
    __nv_bfloat162 h = __float22bfloat162_rn(v);
    float2 hv = __bfloat1622float2(h);
    __nv_bfloat162 l = __float22bfloat162_rn(make_float2(v.x - hv.x, v.y - hv.y));
    hi = *reinterpret_cast<uint32_t*>(&h);
    lo = *reinterpret_cast<uint32_t*>(&l);
}

__global__ void conv_w_kernel(const float* __restrict__ w) {
    const size_t n4   = (size_t)VPAD * KDIM / 4;
    const size_t src4 = (size_t)VDIM * KDIM / 4;
    uint2* dh = reinterpret_cast<uint2*>(g_wh);
    uint2* dl = reinterpret_cast<uint2*>(g_wl);
    const float4* s = reinterpret_cast<const float4*>(w);
    for (size_t i = blockIdx.x * (size_t)blockDim.x + threadIdx.x; i < n4;
         i += (size_t)gridDim.x * blockDim.x) {
        float4 v = (i < src4) ? s[i] : make_float4(0.f, 0.f, 0.f, 0.f);
        uint2 oh, ol;
        split2(make_float2(v.x, v.y), oh.x, ol.x);
        split2(make_float2(v.z, v.w), oh.y, ol.y);
        dh[i] = oh; dl[i] = ol;
    }
}

__global__ void conv_x_kernel(const float* __restrict__ x) {
    const size_t n4 = (size_t)NROWS * KDIM / 4;
    uint2* dh = reinterpret_cast<uint2*>(g_xh);
    uint2* dl = reinterpret_cast<uint2*>(g_xl);
    const float4* s = reinterpret_cast<const float4*>(x);
    for (size_t i = blockIdx.x * (size_t)blockDim.x + threadIdx.x; i < n4;
         i += (size_t)gridDim.x * blockDim.x) {
        float4 v = s[i];
        uint2 oh, ol;
        split2(make_float2(v.x, v.y), oh.x, ol.x);
        split2(make_float2(v.z, v.w), oh.y, ol.y);
        dh[i] = oh; dl[i] = ol;
    }
}

// ---------------- exact fp32 label logit (safe indexing) ----------------
__global__ void zy_kernel(const float* __restrict__ x, const float* __restrict__ w,
                          const void* __restrict__ y) {
    int row  = blockIdx.x * 4 + (threadIdx.x >> 5);
    int lane = threadIdx.x & 31;
    if (row >= NROWS) return;
    int yv = load_label(y, row);
    int cls = (yv < 0) ? 0 : ((yv >= VDIM) ? 0 : yv);   // hard clamp
    const float4* xr = reinterpret_cast<const float4*>(x + (size_t)row * KDIM);
    const float4* wr = reinterpret_cast<const float4*>(w + (size_t)cls * KDIM);
    float s = 0.f;
    #pragma unroll 4
    for (int i = lane; i < KDIM / 4; i += 32) {
        float4 a = xr[i], b = wr[i];
        s += a.x * b.x + a.y * b.y + a.z * b.z + a.w * b.w;
    }
    #pragma unroll
    for (int o = 16; o > 0; o >>= 1) s += __shfl_xor_sync(0xffffffffu, s, o);
    if (lane == 0) g_zy[row] = s;
}

// ---------------- PTX helpers ----------------
__device__ __forceinline__ void cp16(uint32_t dst, const void* src) {
    asm volatile("cp.async.cg.shared.global [%0], [%1], 16;\n" :: "r"(dst), "l"(src));
}
__device__ __forceinline__ void ldsm4(uint32_t* d, uint32_t addr) {
    asm volatile("ldmatrix.sync.aligned.m8n8.x4.shared.b16 {%0,%1,%2,%3}, [%4];"
        : "=r"(d[0]), "=r"(d[1]), "=r"(d[2]), "=r"(d[3]) : "r"(addr));
}
__device__ __forceinline__ void mma16816(float* c, const uint32_t* a, uint32_t b0, uint32_t b1) {
    asm volatile("mma.sync.aligned.m16n8k16.row.col.f32.bf16.bf16.f32 "
        "{%0,%1,%2,%3}, {%4,%5,%6,%7}, {%8,%9}, {%0,%1,%2,%3};"
        : "+f"(c[0]), "+f"(c[1]), "+f"(c[2]), "+f"(c[3])
        : "r"(a[0]), "r"(a[1]), "r"(a[2]), "r"(a[3]), "r"(b0), "r"(b1));
}

// prefetch one K-tile for all 4 operand planes (A_hi, A_lo, B_hi, B_lo)
__device__ __forceinline__ void prefetch_tile(
    const __nv_bfloat16* gAh, const __nv_bfloat16* gAl,
    const __nv_bfloat16* gBh, const __nv_bfloat16* gBl,
    uint32_t stage_base, uint32_t ABYTES, int k0, int tid) {
    #pragma unroll
    for (int i = 0; i < 4; i++) {
        int g = tid + 256 * i;
        int rr = g >> 3;
        int cc = g & 7;
        uint32_t off = rr * (ASTR * 2) + cc * 16;
        size_t src = (size_t)rr * KDIM + k0 + cc * 8;
        cp16(stage_base + 0 * ABYTES + off, gAh + src);
        cp16(stage_base + 1 * ABYTES + off, gAl + src);
        cp16(stage_base + 2 * ABYTES + off, gBh + src);
        cp16(stage_base + 3 * ABYTES + off, gBl + src);
    }
    asm volatile("cp.async.commit_group;\n" ::: "memory");
}

// ---------------- fused split-bf16 GEMM + streaming sum-exp epilogue ----------------
__global__ void __launch_bounds__(256) gemm_ce_kernel() {
    extern __shared__ __align__(16) char smem_raw[];

    const int tid  = threadIdx.x;
    const int lane = tid & 31;
    const int wid  = tid >> 5;
    const int wm   = wid >> 2;
    const int wn   = wid & 3;
    const int bid  = blockIdx.x;
    const int vt   = bid >> 5;   // consecutive bids share vtile -> L2 reuse of W band
    const int rt   = bid & 31;
    const int row0 = rt * BM;
    const int col0 = vt * BN;

    const __nv_bfloat16* gAh = g_xh + (size_t)row0 * KDIM;
    const __nv_bfloat16* gAl = g_xl + (size_t)row0 * KDIM;
    const __nv_bfloat16* gBh = g_wh + (size_t)col0 * KDIM;
    const __nv_bfloat16* gBl = g_wl + (size_t)col0 * KDIM;

    const uint32_t sbase  = (uint32_t)__cvta_generic_to_shared(smem_raw);
    const uint32_t ABYTES = BM * ASTR * 2;       // 18432
    const uint32_t STAGE  = 4 * ABYTES;          // 73728

    float acc[4][4][4];
    #pragma unroll
    for (int i = 0; i < 4; i++)
        #pragma unroll
        for (int j = 0; j < 4; j++)
            #pragma unroll
            for (int k = 0; k < 4; k++) acc[i][j][k] = 0.f;

    prefetch_tile(gAh, gAl, gBh, gBl, sbase, ABYTES, 0, tid);

    const int row_in = lane & 15;
    const int khalf  = (lane >> 4) & 1;
    const uint32_t aoff = ((wm * 64 + row_in) * ASTR + khalf * 8) * 2;
    const uint32_t boff = ((wn * 32 + row_in) * ASTR + khalf * 8) * 2;

    for (int kt = 0; kt < NK; kt++) {
        if (kt + 1 < NK) {
            prefetch_tile(gAh, gAl, gBh, gBl, sbase + ((kt + 1) & 1) * STAGE,
                          ABYTES, (kt + 1) * BK, tid);
            asm volatile("cp.async.wait_group 1;\n" ::: "memory");
        } else {
            asm volatile("cp.async.wait_group 0;\n" ::: "memory");
        }
        __syncthreads();

        const uint32_t s_ah = sbase + (kt & 1) * STAGE;
        const uint32_t s_al = s_ah + ABYTES;
        const uint32_t s_bh = s_al + ABYTES;
        const uint32_t s_bl = s_bh + ABYTES;
        #pragma unroll
        for (int ks = 0; ks < 4; ks++) {
            uint32_t ah[4][4], al[4][4], bh[2][4], bl[2][4];
            #pragma unroll
            for (int mt = 0; mt < 4; mt++) {
                uint32_t o = aoff + mt * (16 * ASTR * 2) + ks * 32;
                ldsm4(ah[mt], s_ah + o);
                ldsm4(al[mt], s_al + o);
            }
            #pragma unroll
            for (int pp = 0; pp < 2; pp++) {
                uint32_t o = boff + pp * (16 * ASTR * 2) + ks * 32;
                ldsm4(bh[pp], s_bh + o);
                ldsm4(bl[pp], s_bl + o);
            }
            #pragma unroll
            for (int mt = 0; mt < 4; mt++) {
                mma16816(acc[mt][0], ah[mt], bh[0][0], bh[0][2]);
                mma16816(acc[mt][1], ah[mt], bh[0][1], bh[0][3]);
                mma16816(acc[mt][2], ah[mt], bh[1][0], bh[1][2]);
                mma16816(acc[mt][3], ah[mt], bh[1][1], bh[1][3]);
                mma16816(acc[mt][0], ah[mt], bl[0][0], bl[0][2]);
                mma16816(acc[mt][1], ah[mt], bl[0][1], bl[0][3]);
                mma16816(acc[mt][2], ah[mt], bl[1][0], bl[1][2]);
                mma16816(acc[mt][3], ah[mt], bl[1][1], bl[1][3]);
                mma16816(acc[mt][0], al[mt], bh[0][0], bh[0][2]);
                mma16816(acc[mt][1], al[mt], bh[0][1], bh[0][3]);
                mma16816(acc[mt][2], al[mt], bh[1][0], bh[1][2]);
                mma16816(acc[mt][3], al[mt], bh[1][1], bh[1][3]);
            }
        }
        __syncthreads();
    }

    // ----- epilogue: per-row sum(exp(z)) over this vtile -----
    float* rs = (float*)smem_raw;   // reuse smem: [4 warp_n][BM]

    #pragma unroll
    for (int mt = 0; mt < 4; mt++) {
        #pragma unroll
        for (int h = 0; h < 2; h++) {
            int lrow = wm * 64 + mt * 16 + (lane >> 2) + h * 8;
            float s = 0.f;
            #pragma unroll
            for (int nt = 0; nt < 4; nt++) {
                #pragma unroll
                for (int j = 0; j < 2; j++) {
                    int col = col0 + wn * 32 + nt * 8 + (lane & 3) * 2 + j;
                    float z = acc[mt][nt][h * 2 + j];
                    if (col < VDIM) s += fast_exp(z);
                }
            }
            s += __shfl_xor_sync(0xffffffffu, s, 1);
            s += __shfl_xor_sync(0xffffffffu, s, 2);
            if ((lane & 3) == 0) rs[wn * BM + lrow] = s;
        }
    }
    __syncthreads();
    if (tid < BM)
        g_spart[(size_t)vt * NROWS + row0 + tid] =
            rs[tid] + rs[BM + tid] + rs[2 * BM + tid] + rs[3 * BM + tid];
}

// ---------------- reduction across vtiles -> per-row NLL ----------------
__global__ void reduce_rows_kernel(const void* __restrict__ y) {
    int row  = blockIdx.x * 8 + (threadIdx.x >> 5);
    int lane = threadIdx.x & 31;
    if (row >= NROWS) return;
    float s = 0.f;
    for (int t = lane; t < VTILES; t += 32) s += g_spart[(size_t)t * NROWS + row];
    #pragma unroll
    for (int o = 16; o > 0; o >>= 1) s += __shfl_xor_sync(0xffffffffu, s, o);
    if (lane == 0) {
        int yv = load_label(y, row);
        bool valid = (yv != IGNORE_IDX);
        float nll = logf(s) - g_zy[row];
        g_nll[row] = valid ? nll : 0.f;
        g_vld[row] = valid ? 1.f : 0.f;
    }
}

// ---------------- deterministic final reduction ----------------
__global__ void finalize_kernel(float* __restrict__ out) {
    __shared__ float ss[256], sc[256];
    int t = threadIdx.x;
    float s = 0.f, c = 0.f;
    for (int i = t; i < NROWS; i += 256) { s += g_nll[i]; c += g_vld[i]; }
    ss[t] = s; sc[t] = c;
    __syncthreads();
    for (int o = 128; o > 0; o >>= 1) {
        if (t < o) { ss[t] += ss[t + o]; sc[t] += sc[t + o]; }
        __syncthreads();
    }
    if (t == 0) out[0] = ss[0] / fmaxf(sc[0], 1.f);
}

// ---------------- launcher ----------------
extern "C" void kernel_launch(void* const* d_in, const int* in_sizes, int n_in,
                              void* d_out, int out_size) {
    const float* x = (const float*)d_in[0];
    const float* w = (const float*)d_in[1];
    const void*  y = d_in[2];
    for (int i = 0; i < n_in; i++) {
        if (in_sizes[i] == NROWS)              y = d_in[i];
        else if (in_sizes[i] == NROWS * KDIM)  x = (const float*)d_in[i];
        else                                   w = (const float*)d_in[i];
    }

    cudaFuncSetAttribute(gemm_ce_kernel,
                         cudaFuncAttributeMaxDynamicSharedMemorySize, 147456);

    detect_y_kernel<<<1, 256>>>((const int*)y);
    conv_w_kernel<<<4096, 256>>>(w);
    conv_x_kernel<<<2048, 256>>>(x);
    zy_kernel<<<NROWS / 4, 128>>>(x, w, y);
    gemm_ce_kernel<<<VTILES * 32, 256, 147456>>>();
    reduce_rows_kernel<<<NROWS / 8, 256>>>(y);
    finalize_kernel<<<1, 256>>>((float*)d_out);
}

// round 10
// speedup vs baseline: 2.1862x; 2.1862x over previous
#include <cuda_runtime.h>
#include <cuda_bf16.h>
#include <cstdint>
#include <cstddef>

#define NROWS 4096
#define KDIM  2048
#define VDIM  50257
#define BM 128
#define BN 128
#define BK 64
#define VTILES ((VDIM + BN - 1) / BN)   /* 393 */
#define VPAD   (VTILES * BN)            /* 50304 */
#define ASTR   72                       /* halves per smem row (64 + 8 pad) */
#define NK     (KDIM / BK)              /* 32 */
#define NSTAGE 4
#define IGNORE_IDX (-100)

// ---------------- device scratch (static: no allocations allowed) ----------------
__device__ __nv_bfloat16 g_wb[(size_t)VPAD * KDIM];     // bf16 weight
__device__ __nv_bfloat16 g_xb[(size_t)NROWS * KDIM];    // bf16 x
__device__ float g_spart[(size_t)VTILES * NROWS];       // partial sum-exp per (vtile,row)
__device__ float g_zy[NROWS];                           // exact fp32 logit at label
__device__ float g_nll[NROWS];
__device__ float g_vld[NROWS];
__device__ int   g_y64;                                 // 1 if labels are int64, 0 if int32

// ---------------- label dtype probe ----------------
// int64 (LE, labels < 2^31): every odd int32 word is a zero hi-word.
__global__ void detect_y_kernel(const int* __restrict__ y32) {
    __shared__ int any_nonzero;
    if (threadIdx.x == 0) any_nonzero = 0;
    __syncthreads();
    for (int i = threadIdx.x; i < NROWS / 2; i += blockDim.x)
        if (y32[2 * i + 1] != 0) any_nonzero = 1;
    __syncthreads();
    if (threadIdx.x == 0) g_y64 = any_nonzero ? 0 : 1;
}

__device__ __forceinline__ int load_label(const void* y, int row) {
    if (g_y64) return (int)((const long long*)y)[row];
    return ((const int*)y)[row];
}

// ---------------- fast exp: FFMA polynomial, avoids MUFU bottleneck ----------------
__device__ __forceinline__ float fast_exp(float x) {
    x = fminf(fmaxf(x, -80.f), 80.f);
    float n = rintf(x * 1.4426950408889634f);
    float r = fmaf(n, -0.693145751953125f, x);
    r = fmaf(n, -1.428606765330187e-06f, r);
    float p = 8.3333333e-3f;
    p = fmaf(p, r, 4.1666667e-2f);
    p = fmaf(p, r, 1.6666667e-1f);
    p = fmaf(p, r, 0.5f);
    p = fmaf(p, r, 1.0f);
    p = fmaf(p, r, 1.0f);
    return __int_as_float(__float_as_int(p) + (((int)n) << 23));
}

// ---------------- conversion kernels ----------------
__global__ void conv_w_kernel(const float* __restrict__ w) {
    const size_t n4   = (size_t)VPAD * KDIM / 4;
    const size_t src4 = (size_t)VDIM * KDIM / 4;
    uint2* dst = reinterpret_cast<uint2*>(g_wb);
    const float4* s = reinterpret_cast<const float4*>(w);
    for (size_t i = blockIdx.x * (size_t)blockDim.x + threadIdx.x; i < n4;
         i += (size_t)gridDim.x * blockDim.x) {
        float4 v = (i < src4) ? s[i] : make_float4(0.f, 0.f, 0.f, 0.f);
        __nv_bfloat162 lo = __float22bfloat162_rn(make_float2(v.x, v.y));
        __nv_bfloat162 hi = __float22bfloat162_rn(make_float2(v.z, v.w));
        uint2 o;
        o.x = *reinterpret_cast<uint32_t*>(&lo);
        o.y = *reinterpret_cast<uint32_t*>(&hi);
        dst[i] = o;
    }
}

__global__ void conv_x_kernel(const float* __restrict__ x) {
    const size_t n4 = (size_t)NROWS * KDIM / 4;
    uint2* dst = reinterpret_cast<uint2*>(g_xb);
    const float4* s = reinterpret_cast<const float4*>(x);
    for (size_t i = blockIdx.x * (size_t)blockDim.x + threadIdx.x; i < n4;
         i += (size_t)gridDim.x * blockDim.x) {
        float4 v = s[i];
        __nv_bfloat162 lo = __float22bfloat162_rn(make_float2(v.x, v.y));
        __nv_bfloat162 hi = __float22bfloat162_rn(make_float2(v.z, v.w));
        uint2 o;
        o.x = *reinterpret_cast<uint32_t*>(&lo);
        o.y = *reinterpret_cast<uint32_t*>(&hi);
        dst[i] = o;
    }
}

// ---------------- exact fp32 label logit (safe indexing) ----------------
__global__ void zy_kernel(const float* __restrict__ x, const float* __restrict__ w,
                          const void* __restrict__ y) {
    int row  = blockIdx.x * 4 + (threadIdx.x >> 5);
    int lane = threadIdx.x & 31;
    if (row >= NROWS) return;
    int yv = load_label(y, row);
    int cls = (yv < 0) ? 0 : ((yv >= VDIM) ? 0 : yv);   // hard clamp
    const float4* xr = reinterpret_cast<const float4*>(x + (size_t)row * KDIM);
    const float4* wr = reinterpret_cast<const float4*>(w + (size_t)cls * KDIM);
    float s = 0.f;
    #pragma unroll 4
    for (int i = lane; i < KDIM / 4; i += 32) {
        float4 a = xr[i], b = wr[i];
        s += a.x * b.x + a.y * b.y + a.z * b.z + a.w * b.w;
    }
    #pragma unroll
    for (int o = 16; o > 0; o >>= 1) s += __shfl_xor_sync(0xffffffffu, s, o);
    if (lane == 0) g_zy[row] = s;
}

// ---------------- PTX helpers ----------------
__device__ __forceinline__ void cp16(uint32_t dst, const void* src) {
    asm volatile("cp.async.cg.shared.global [%0], [%1], 16;\n" :: "r"(dst), "l"(src));
}
__device__ __forceinline__ void ldsm4(uint32_t* d, uint32_t addr) {
    asm volatile("ldmatrix.sync.aligned.m8n8.x4.shared.b16 {%0,%1,%2,%3}, [%4];"
        : "=r"(d[0]), "=r"(d[1]), "=r"(d[2]), "=r"(d[3]) : "r"(addr));
}
__device__ __forceinline__ void mma16816(float* c, const uint32_t* a, uint32_t b0, uint32_t b1) {
    asm volatile("mma.sync.aligned.m16n8k16.row.col.f32.bf16.bf16.f32 "
        "{%0,%1,%2,%3}, {%4,%5,%6,%7}, {%8,%9}, {%0,%1,%2,%3};"
        : "+f"(c[0]), "+f"(c[1]), "+f"(c[2]), "+f"(c[3])
        : "r"(a[0]), "r"(a[1]), "r"(a[2]), "r"(a[3]), "r"(b0), "r"(b1));
}

// prefetch one K-tile: A plane + B plane
__device__ __forceinline__ void prefetch_tile(const __nv_bfloat16* gA, const __nv_bfloat16* gB,
                                              uint32_t stage_base, uint32_t ABYTES,
                                              int k0, int tid) {
    #pragma unroll
    for (int i = 0; i < 4; i++) {
        int g = tid + 256 * i;
        int rr = g >> 3;
        int cc = g & 7;
        uint32_t off = rr * (ASTR * 2) + cc * 16;
        size_t src = (size_t)rr * KDIM + k0 + cc * 8;
        cp16(stage_base + off, gA + src);
        cp16(stage_base + ABYTES + off, gB + src);
    }
    asm volatile("cp.async.commit_group;\n" ::: "memory");
}

// ---------------- fused bf16 GEMM + streaming sum-exp epilogue ----------------
__global__ void __launch_bounds__(256) gemm_ce_kernel() {
    extern __shared__ __align__(16) char smem_raw[];

    const int tid  = threadIdx.x;
    const int lane = tid & 31;
    const int wid  = tid >> 5;
    const int wm   = wid >> 2;
    const int wn   = wid & 3;
    const int bid  = blockIdx.x;
    const int vt   = bid >> 5;   // consecutive bids share vtile -> L2 reuse of W band
    const int rt   = bid & 31;
    const int row0 = rt * BM;
    const int col0 = vt * BN;

    const __nv_bfloat16* gA = g_xb + (size_t)row0 * KDIM;
    const __nv_bfloat16* gB = g_wb + (size_t)col0 * KDIM;

    const uint32_t sbase  = (uint32_t)__cvta_generic_to_shared(smem_raw);
    const uint32_t ABYTES = BM * ASTR * 2;       // 18432
    const uint32_t STAGE  = 2 * ABYTES;          // 36864 (A+B)

    float acc[4][4][4];
    #pragma unroll
    for (int i = 0; i < 4; i++)
        #pragma unroll
        for (int j = 0; j < 4; j++)
            #pragma unroll
            for (int k = 0; k < 4; k++) acc[i][j][k] = 0.f;

    // prime stages 0..NSTAGE-2
    #pragma unroll
    for (int p = 0; p < NSTAGE - 1; p++)
        prefetch_tile(gA, gB, sbase + p * STAGE, ABYTES, p * BK, tid);

    const int row_in = lane & 15;
    const int khalf  = (lane >> 4) & 1;
    const uint32_t aoff = ((wm * 64 + row_in) * ASTR + khalf * 8) * 2;
    const uint32_t boff = ((wn * 32 + row_in) * ASTR + khalf * 8) * 2;

    int stage = 0;
    for (int kt = 0; kt < NK; kt++) {
        if (kt + NSTAGE - 1 < NK) {
            int ps = stage + NSTAGE - 1; if (ps >= NSTAGE) ps -= NSTAGE;
            prefetch_tile(gA, gB, sbase + ps * STAGE, ABYTES, (kt + NSTAGE - 1) * BK, tid);
            asm volatile("cp.async.wait_group %0;\n" :: "n"(NSTAGE - 1) : "memory");
        } else {
            // drain: remaining in-flight groups for kt..NK-1
            int rem = NK - 1 - kt;
            if (rem >= 2)      asm volatile("cp.async.wait_group 2;\n" ::: "memory");
            else if (rem == 1) asm volatile("cp.async.wait_group 1;\n" ::: "memory");
            else               asm volatile("cp.async.wait_group 0;\n" ::: "memory");
        }
        __syncthreads();

        const uint32_t as = sbase + stage * STAGE;
        const uint32_t bs = as + ABYTES;
        #pragma unroll
        for (int ks = 0; ks < 4; ks++) {
            uint32_t a[4][4], b[2][4];
            #pragma unroll
            for (int mt = 0; mt < 4; mt++)
                ldsm4(a[mt], as + aoff + mt * (16 * ASTR * 2) + ks * 32);
            #pragma unroll
            for (int pp = 0; pp < 2; pp++)
                ldsm4(b[pp], bs + boff + pp * (16 * ASTR * 2) + ks * 32);
            #pragma unroll
            for (int mt = 0; mt < 4; mt++) {
                mma16816(acc[mt][0], a[mt], b[0][0], b[0][2]);
                mma16816(acc[mt][1], a[mt], b[0][1], b[0][3]);
                mma16816(acc[mt][2], a[mt], b[1][0], b[1][2]);
                mma16816(acc[mt][3], a[mt], b[1][1], b[1][3]);
            }
        }
        __syncthreads();
        if (++stage >= NSTAGE) stage = 0;
    }

    // ----- epilogue: per-row sum(exp(z)) over this vtile -----
    float* rs = (float*)smem_raw;   // reuse smem: [4 warp_n][BM]

    #pragma unroll
    for (int mt = 0; mt < 4; mt++) {
        #pragma unroll
        for (int h = 0; h < 2; h++) {
            int lrow = wm * 64 + mt * 16 + (lane >> 2) + h * 8;
            float s = 0.f;
            #pragma unroll
            for (int nt = 0; nt < 4; nt++) {
                #pragma unroll
                for (int j = 0; j < 2; j++) {
                    int col = col0 + wn * 32 + nt * 8 + (lane & 3) * 2 + j;
                    float z = acc[mt][nt][h * 2 + j];
                    if (col < VDIM) s += fast_exp(z);
                }
            }
            s += __shfl_xor_sync(0xffffffffu, s, 1);
            s += __shfl_xor_sync(0xffffffffu, s, 2);
            if ((lane & 3) == 0) rs[wn * BM + lrow] = s;
        }
    }
    __syncthreads();
    if (tid < BM)
        g_spart[(size_t)vt * NROWS + row0 + tid] =
            rs[tid] + rs[BM + tid] + rs[2 * BM + tid] + rs[3 * BM + tid];
}

// ---------------- reduction across vtiles -> per-row NLL ----------------
__global__ void reduce_rows_kernel(const void* __restrict__ y) {
    int row  = blockIdx.x * 8 + (threadIdx.x >> 5);
    int lane = threadIdx.x & 31;
    if (row >= NROWS) return;
    float s = 0.f;
    for (int t = lane; t < VTILES; t += 32) s += g_spart[(size_t)t * NROWS + row];
    #pragma unroll
    for (int o = 16; o > 0; o >>= 1) s += __shfl_xor_sync(0xffffffffu, s, o);
    if (lane == 0) {
        int yv = load_label(y, row);
        bool valid = (yv != IGNORE_IDX);
        float nll = logf(s) - g_zy[row];
        g_nll[row] = valid ? nll : 0.f;
        g_vld[row] = valid ? 1.f : 0.f;
    }
}

// ---------------- deterministic final reduction ----------------
__global__ void finalize_kernel(float* __restrict__ out) {
    __shared__ float ss[256], sc[256];
    int t = threadIdx.x;
    float s = 0.f, c = 0.f;
    for (int i = t; i < NROWS; i += 256) { s += g_nll[i]; c += g_vld[i]; }
    ss[t] = s; sc[t] = c;
    __syncthreads();
    for (int o = 128; o > 0; o >>= 1) {
        if (t < o) { ss[t] += ss[t + o]; sc[t] += sc[t + o]; }
        __syncthreads();
    }
    if (t == 0) out[0] = ss[0] / fmaxf(sc[0], 1.f);
}

// ---------------- launcher ----------------
extern "C" void kernel_launch(void* const* d_in, const int* in_sizes, int n_in,
                              void* d_out, int out_size) {
    const float* x = (const float*)d_in[0];
    const float* w = (const float*)d_in[1];
    const void*  y = d_in[2];
    for (int i = 0; i < n_in; i++) {
        if (in_sizes[i] == NROWS)              y = d_in[i];
        else if (in_sizes[i] == NROWS * KDIM)  x = (const float*)d_in[i];
        else                                   w = (const float*)d_in[i];
    }

    cudaFuncSetAttribute(gemm_ce_kernel,
                         cudaFuncAttributeMaxDynamicSharedMemorySize, NSTAGE * 36864);

    detect_y_kernel<<<1, 256>>>((const int*)y);
    conv_w_kernel<<<4096, 256>>>(w);
    conv_x_kernel<<<2048, 256>>>(x);
    zy_kernel<<<NROWS / 4, 128>>>(x, w, y);
    gemm_ce_kernel<<<VTILES * 32, 256, NSTAGE * 36864>>>();
    reduce_rows_kernel<<<NROWS / 8, 256>>>(y);
    finalize_kernel<<<1, 256>>>((float*)d_out);
}

// round 16
// speedup vs baseline: 2.6669x; 1.2199x over previous
#include <cuda_runtime.h>
#include <cuda_bf16.h>
#include <cstdint>
#include <cstddef>

#define NROWS 4096
#define KDIM  2048
#define VDIM  50257
#define BM 256
#define BN 128
#define BK 64
#define NTHREADS 512
#define VTILES ((VDIM + BN - 1) / BN)   /* 393 */
#define VPAD   (VTILES * BN)            /* 50304 */
#define ASTR   72                       /* halves per smem row (64 + 8 pad) */
#define NK     (KDIM / BK)              /* 32 */
#define NSTAGE 3
#define IGNORE_IDX (-100)

#define ABYTES_A (BM * ASTR * 2)        /* 36864 */
#define ABYTES_B (BN * ASTR * 2)        /* 18432 */
#define STAGE    (ABYTES_A + ABYTES_B)  /* 55296 */
#define SMEM_REQ (NSTAGE * STAGE)       /* 165888 */

// ---------------- device scratch (static: no allocations allowed) ----------------
__device__ __nv_bfloat16 g_wb[(size_t)VPAD * KDIM];     // bf16 weight
__device__ __nv_bfloat16 g_xb[(size_t)NROWS * KDIM];    // bf16 x
__device__ float g_spart[(size_t)VTILES * NROWS];       // partial sum-exp per (vtile,row)
__device__ float g_zy[NROWS];                           // exact fp32 logit at label
__device__ float g_nll[NROWS];
__device__ float g_vld[NROWS];
__device__ int   g_y64;                                 // 1 if labels are int64, 0 if int32

// ---------------- label dtype probe ----------------
__global__ void detect_y_kernel(const int* __restrict__ y32) {
    __shared__ int any_nonzero;
    if (threadIdx.x == 0) any_nonzero = 0;
    __syncthreads();
    for (int i = threadIdx.x; i < NROWS / 2; i += blockDim.x)
        if (y32[2 * i + 1] != 0) any_nonzero = 1;
    __syncthreads();
    if (threadIdx.x == 0) g_y64 = any_nonzero ? 0 : 1;
}
__device__ __forceinline__ int load_label(const void* y, int row) {
    if (g_y64) return (int)((const long long*)y)[row];
    return ((const int*)y)[row];
}

// ---------------- fast exp: FFMA polynomial, avoids MUFU bottleneck ----------------
__device__ __forceinline__ float fast_exp(float x) {
    x = fminf(fmaxf(x, -80.f), 80.f);
    float n = rintf(x * 1.4426950408889634f);
    float r = fmaf(n, -0.693145751953125f, x);
    r = fmaf(n, -1.428606765330187e-06f, r);
    float p = 8.3333333e-3f;
    p = fmaf(p, r, 4.1666667e-2f);
    p = fmaf(p, r, 1.6666667e-1f);
    p = fmaf(p, r, 0.5f);
    p = fmaf(p, r, 1.0f);
    p = fmaf(p, r, 1.0f);
    return __int_as_float(__float_as_int(p) + (((int)n) << 23));
}

// ---------------- conversion kernels ----------------
__global__ void conv_w_kernel(const float* __restrict__ w) {
    const size_t n4   = (size_t)VPAD * KDIM / 4;
    const size_t src4 = (size_t)VDIM * KDIM / 4;
    uint2* dst = reinterpret_cast<uint2*>(g_wb);
    const float4* s = reinterpret_cast<const float4*>(w);
    for (size_t i = blockIdx.x * (size_t)blockDim.x + threadIdx.x; i < n4;
         i += (size_t)gridDim.x * blockDim.x) {
        float4 v = (i < src4) ? s[i] : make_float4(0.f, 0.f, 0.f, 0.f);
        __nv_bfloat162 lo = __float22bfloat162_rn(make_float2(v.x, v.y));
        __nv_bfloat162 hi = __float22bfloat162_rn(make_float2(v.z, v.w));
        uint2 o;
        o.x = *reinterpret_cast<uint32_t*>(&lo);
        o.y = *reinterpret_cast<uint32_t*>(&hi);
        dst[i] = o;
    }
}
__global__ void conv_x_kernel(const float* __restrict__ x) {
    const size_t n4 = (size_t)NROWS * KDIM / 4;
    uint2* dst = reinterpret_cast<uint2*>(g_xb);
    const float4* s = reinterpret_cast<const float4*>(x);
    for (size_t i = blockIdx.x * (size_t)blockDim.x + threadIdx.x; i < n4;
         i += (size_t)gridDim.x * blockDim.x) {
        float4 v = s[i];
        __nv_bfloat162 lo = __float22bfloat162_rn(make_float2(v.x, v.y));
        __nv_bfloat162 hi = __float22bfloat162_rn(make_float2(v.z, v.w));
        uint2 o;
        o.x = *reinterpret_cast<uint32_t*>(&lo);
        o.y = *reinterpret_cast<uint32_t*>(&hi);
        dst[i] = o;
    }
}

// ---------------- exact fp32 label logit (safe indexing) ----------------
__global__ void zy_kernel(const float* __restrict__ x, const float* __restrict__ w,
                          const void* __restrict__ y) {
    int row  = blockIdx.x * 4 + (threadIdx.x >> 5);
    int lane = threadIdx.x & 31;
    if (row >= NROWS) return;
    int yv = load_label(y, row);
    int cls = (yv < 0) ? 0 : ((yv >= VDIM) ? 0 : yv);   // hard clamp
    const float4* xr = reinterpret_cast<const float4*>(x + (size_t)row * KDIM);
    const float4* wr = reinterpret_cast<const float4*>(w + (size_t)cls * KDIM);
    float s = 0.f;
    #pragma unroll 4
    for (int i = lane; i < KDIM / 4; i += 32) {
        float4 a = xr[i], b = wr[i];
        s += a.x * b.x + a.y * b.y + a.z * b.z + a.w * b.w;
    }
    #pragma unroll
    for (int o = 16; o > 0; o >>= 1) s += __shfl_xor_sync(0xffffffffu, s, o);
    if (lane == 0) g_zy[row] = s;
}

// ---------------- PTX helpers ----------------
__device__ __forceinline__ void cp16(uint32_t dst, const void* src) {
    asm volatile("cp.async.cg.shared.global [%0], [%1], 16;\n" :: "r"(dst), "l"(src));
}
__device__ __forceinline__ void ldsm4(uint32_t* d, uint32_t addr) {
    asm volatile("ldmatrix.sync.aligned.m8n8.x4.shared.b16 {%0,%1,%2,%3}, [%4];"
        : "=r"(d[0]), "=r"(d[1]), "=r"(d[2]), "=r"(d[3]) : "r"(addr));
}
__device__ __forceinline__ void mma16816(float* c, const uint32_t* a, uint32_t b0, uint32_t b1) {
    asm volatile("mma.sync.aligned.m16n8k16.row.col.f32.bf16.bf16.f32 "
        "{%0,%1,%2,%3}, {%4,%5,%6,%7}, {%8,%9}, {%0,%1,%2,%3};"
        : "+f"(c[0]), "+f"(c[1]), "+f"(c[2]), "+f"(c[3])
        : "r"(a[0]), "r"(a[1]), "r"(a[2]), "r"(a[3]), "r"(b0), "r"(b1));
}

// prefetch one K-tile: A (256 rows) + B (128 rows), 512 threads
__device__ __forceinline__ void prefetch_tile(const __nv_bfloat16* gA, const __nv_bfloat16* gB,
                                              uint32_t stage_base, int k0, int tid) {
    #pragma unroll
    for (int i = 0; i < 4; i++) {               // A: 256 rows x 8 chunks = 2048
        int g = tid + NTHREADS * i;
        int rr = g >> 3;
        int cc = g & 7;
        uint32_t off = rr * (ASTR * 2) + cc * 16;
        cp16(stage_base + off, gA + (size_t)rr * KDIM + k0 + cc * 8);
    }
    #pragma unroll
    for (int i = 0; i < 2; i++) {               // B: 128 rows x 8 chunks = 1024
        int g = tid + NTHREADS * i;
        int rr = g >> 3;
        int cc = g & 7;
        uint32_t off = rr * (ASTR * 2) + cc * 16;
        cp16(stage_base + ABYTES_A + off, gB + (size_t)rr * KDIM + k0 + cc * 8);
    }
    asm volatile("cp.async.commit_group;\n" ::: "memory");
}

// ---------------- fused bf16 GEMM + streaming sum-exp epilogue ----------------
__global__ void __launch_bounds__(NTHREADS) gemm_ce_kernel() {
    extern __shared__ __align__(16) char smem_raw[];

    const int tid  = threadIdx.x;
    const int lane = tid & 31;
    const int wid  = tid >> 5;
    const int wm   = wid >> 2;   // 0..3 (M dim of warp grid)
    const int wn   = wid & 3;    // 0..3 (N dim)
    const int bid  = blockIdx.x;
    const int vt   = bid >> 4;   // 16 consecutive bids share vtile -> L2 reuse of W band
    const int rt   = bid & 15;
    const int row0 = rt * BM;
    const int col0 = vt * BN;

    const __nv_bfloat16* gA = g_xb + (size_t)row0 * KDIM;
    const __nv_bfloat16* gB = g_wb + (size_t)col0 * KDIM;

    const uint32_t sbase = (uint32_t)__cvta_generic_to_shared(smem_raw);

    float acc[4][4][4];
    #pragma unroll
    for (int i = 0; i < 4; i++)
        #pragma unroll
        for (int j = 0; j < 4; j++)
            #pragma unroll
            for (int k = 0; k < 4; k++) acc[i][j][k] = 0.f;

    // prime stages 0..NSTAGE-2
    #pragma unroll
    for (int p = 0; p < NSTAGE - 1; p++)
        prefetch_tile(gA, gB, sbase + p * STAGE, p * BK, tid);

    const int row_in = lane & 15;
    const int khalf  = (lane >> 4) & 1;
    const uint32_t aoff = ((wm * 64 + row_in) * ASTR + khalf * 8) * 2;
    const uint32_t boff = ((wn * 32 + row_in) * ASTR + khalf * 8) * 2;

    int stage = 0;
    for (int kt = 0; kt < NK; kt++) {
        if (kt + NSTAGE - 1 < NK) {
            int ps = stage + NSTAGE - 1; if (ps >= NSTAGE) ps -= NSTAGE;
            prefetch_tile(gA, gB, sbase + ps * STAGE, (kt + NSTAGE - 1) * BK, tid);
            asm volatile("cp.async.wait_group %0;\n" :: "n"(NSTAGE - 1) : "memory");
        } else {
            int rem = NK - 1 - kt;
            if (rem >= 1) asm volatile("cp.async.wait_group 1;\n" ::: "memory");
            else          asm volatile("cp.async.wait_group 0;\n" ::: "memory");
        }
        __syncthreads();

        const uint32_t as = sbase + stage * STAGE;
        const uint32_t bs = as + ABYTES_A;
        #pragma unroll
        for (int ks = 0; ks < 4; ks++) {
            uint32_t a[4][4], b[2][4];
            #pragma unroll
            for (int mt = 0; mt < 4; mt++)
                ldsm4(a[mt], as + aoff + mt * (16 * ASTR * 2) + ks * 32);
            #pragma unroll
            for (int pp = 0; pp < 2; pp++)
                ldsm4(b[pp], bs + boff + pp * (16 * ASTR * 2) + ks * 32);
            #pragma unroll
            for (int mt = 0; mt < 4; mt++) {
                mma16816(acc[mt][0], a[mt], b[0][0], b[0][2]);
                mma16816(acc[mt][1], a[mt], b[0][1], b[0][3]);
                mma16816(acc[mt][2], a[mt], b[1][0], b[1][2]);
                mma16816(acc[mt][3], a[mt], b[1][1], b[1][3]);
            }
        }
        __syncthreads();
        if (++stage >= NSTAGE) stage = 0;
    }

    // ----- epilogue: per-row sum(exp(z)) over this vtile -----
    float* rs = (float*)smem_raw;   // reuse smem: [4 warp_n][BM]

    #pragma unroll
    for (int mt = 0; mt < 4; mt++) {
        #pragma unroll
        for (int h = 0; h < 2; h++) {
            int lrow = wm * 64 + mt * 16 + (lane >> 2) + h * 8;
            float s = 0.f;
            #pragma unroll
            for (int nt = 0; nt < 4; nt++) {
                #pragma unroll
                for (int j = 0; j < 2; j++) {
                    int col = col0 + wn * 32 + nt * 8 + (lane & 3) * 2 + j;
                    float z = acc[mt][nt][h * 2 + j];
                    if (col < VDIM) s += fast_exp(z);
                }
            }
            s += __shfl_xor_sync(0xffffffffu, s, 1);
            s += __shfl_xor_sync(0xffffffffu, s, 2);
            if ((lane & 3) == 0) rs[wn * BM + lrow] = s;
        }
    }
    __syncthreads();
    if (tid < BM)
        g_spart[(size_t)vt * NROWS + row0 + tid] =
            rs[tid] + rs[BM + tid] + rs[2 * BM + tid] + rs[3 * BM + tid];
}

// ---------------- reduction across vtiles -> per-row NLL ----------------
__global__ void reduce_rows_kernel(const void* __restrict__ y) {
    int row  = blockIdx.x * 8 + (threadIdx.x >> 5);
    int lane = threadIdx.x & 31;
    if (row >= NROWS) return;
    float s = 0.f;
    for (int t = lane; t < VTILES; t += 32) s += g_spart[(size_t)t * NROWS + row];
    #pragma unroll
    for (int o = 16; o > 0; o >>= 1) s += __shfl_xor_sync(0xffffffffu, s, o);
    if (lane == 0) {
        int yv = load_label(y, row);
        bool valid = (yv != IGNORE_IDX);
        float nll = logf(s) - g_zy[row];
        g_nll[row] = valid ? nll : 0.f;
        g_vld[row] = valid ? 1.f : 0.f;
    }
}

// ---------------- deterministic final reduction ----------------
__global__ void finalize_kernel(float* __restrict__ out) {
    __shared__ float ss[256], sc[256];
    int t = threadIdx.x;
    float s = 0.f, c = 0.f;
    for (int i = t; i < NROWS; i += 256) { s += g_nll[i]; c += g_vld[i]; }
    ss[t] = s; sc[t] = c;
    __syncthreads();
    for (int o = 128; o > 0; o >>= 1) {
        if (t < o) { ss[t] += ss[t + o]; sc[t] += sc[t + o]; }
        __syncthreads();
    }
    if (t == 0) out[0] = ss[0] / fmaxf(sc[0], 1.f);
}

// ---------------- launcher ----------------
extern "C" void kernel_launch(void* const* d_in, const int* in_sizes, int n_in,
                              void* d_out, int out_size) {
    const float* x = (const float*)d_in[0];
    const float* w = (const float*)d_in[1];
    const void*  y = d_in[2];
    for (int i = 0; i < n_in; i++) {
        if (in_sizes[i] == NROWS)              y = d_in[i];
        else if (in_sizes[i] == NROWS * KDIM)  x = (const float*)d_in[i];
        else                                   w = (const float*)d_in[i];
    }

    cudaFuncSetAttribute(gemm_ce_kernel,
                         cudaFuncAttributeMaxDynamicSharedMemorySize, SMEM_REQ);

    detect_y_kernel<<<1, 256>>>((const int*)y);
    conv_w_kernel<<<4096, 256>>>(w);
    conv_x_kernel<<<2048, 256>>>(x);
    zy_kernel<<<NROWS / 4, 128>>>(x, w, y);
    gemm_ce_kernel<<<VTILES * (NROWS / BM), NTHREADS, SMEM_REQ>>>();
    reduce_rows_kernel<<<NROWS / 8, 256>>>(y);
    finalize_kernel<<<1, 256>>>((float*)d_out);
}

// round 17
// speedup vs baseline: 2.9221x; 1.0957x over previous
#include <cuda_runtime.h>
#include <cuda_bf16.h>
#include <cuda_fp8.h>
#include <cstdint>
#include <cstddef>

#define NROWS 4096
#define KDIM  2048
#define VDIM  50257
#define BM 256
#define BN 128
#define BK 128                           /* fp8 elements per K-stage */
#define NTHREADS 512
#define VTILES ((VDIM + BN - 1) / BN)   /* 393 */
#define VPAD   (VTILES * BN)            /* 50304 */
#define ROWB   144                      /* bytes per smem row: 128 data + 16 pad */
#define NK     (KDIM / BK)              /* 16 */
#define NSTAGE 3
#define IGNORE_IDX (-100)

#define ABYTES_A (BM * ROWB)            /* 36864 */
#define ABYTES_B (BN * ROWB)            /* 18432 */
#define STAGE    (ABYTES_A + ABYTES_B)  /* 55296 */
#define SMEM_REQ (NSTAGE * STAGE)       /* 165888 */

// ---------------- device scratch (static: no allocations allowed) ----------------
__device__ uint8_t g_wb[(size_t)VPAD * KDIM];    // e4m3 weight
__device__ uint8_t g_xb[(size_t)NROWS * KDIM];   // e4m3 x
__device__ float g_spart[(size_t)VTILES * NROWS];
__device__ float g_zy[NROWS];                    // exact fp32 logit at label
__device__ float g_nll[NROWS];
__device__ float g_vld[NROWS];
__device__ int   g_y64;

// ---------------- label dtype probe ----------------
__global__ void detect_y_kernel(const int* __restrict__ y32) {
    __shared__ int any_nonzero;
    if (threadIdx.x == 0) any_nonzero = 0;
    __syncthreads();
    for (int i = threadIdx.x; i < NROWS / 2; i += blockDim.x)
        if (y32[2 * i + 1] != 0) any_nonzero = 1;
    __syncthreads();
    if (threadIdx.x == 0) g_y64 = any_nonzero ? 0 : 1;
}
__device__ __forceinline__ int load_label(const void* y, int row) {
    if (g_y64) return (int)((const long long*)y)[row];
    return ((const int*)y)[row];
}

// ---------------- fast exp (FFMA-only) ----------------
__device__ __forceinline__ float fast_exp(float x) {
    x = fminf(fmaxf(x, -80.f), 80.f);
    float n = rintf(x * 1.4426950408889634f);
    float r = fmaf(n, -0.693145751953125f, x);
    r = fmaf(n, -1.428606765330187e-06f, r);
    float p = 8.3333333e-3f;
    p = fmaf(p, r, 4.1666667e-2f);
    p = fmaf(p, r, 1.6666667e-1f);
    p = fmaf(p, r, 0.5f);
    p = fmaf(p, r, 1.0f);
    p = fmaf(p, r, 1.0f);
    return __int_as_float(__float_as_int(p) + (((int)n) << 23));
}

// ---------------- fp32 -> e4m3 conversions ----------------
__device__ __forceinline__ uint32_t pack_fp8x4(float4 v) {
    __nv_fp8x2_storage_t lo = __nv_cvt_float2_to_fp8x2(make_float2(v.x, v.y),
                                                       __NV_SATFINITE, __NV_E4M3);
    __nv_fp8x2_storage_t hi = __nv_cvt_float2_to_fp8x2(make_float2(v.z, v.w),
                                                       __NV_SATFINITE, __NV_E4M3);
    return (uint32_t)lo | ((uint32_t)hi << 16);
}

__global__ void conv_w_kernel(const float* __restrict__ w) {
    const size_t n4   = (size_t)VPAD * KDIM / 4;
    const size_t src4 = (size_t)VDIM * KDIM / 4;
    uint32_t* dst = reinterpret_cast<uint32_t*>(g_wb);
    const float4* s = reinterpret_cast<const float4*>(w);
    for (size_t i = blockIdx.x * (size_t)blockDim.x + threadIdx.x; i < n4;
         i += (size_t)gridDim.x * blockDim.x) {
        float4 v = (i < src4) ? s[i] : make_float4(0.f, 0.f, 0.f, 0.f);
        dst[i] = pack_fp8x4(v);
    }
}
__global__ void conv_x_kernel(const float* __restrict__ x) {
    const size_t n4 = (size_t)NROWS * KDIM / 4;
    uint32_t* dst = reinterpret_cast<uint32_t*>(g_xb);
    const float4* s = reinterpret_cast<const float4*>(x);
    for (size_t i = blockIdx.x * (size_t)blockDim.x + threadIdx.x; i < n4;
         i += (size_t)gridDim.x * blockDim.x) {
        dst[i] = pack_fp8x4(s[i]);
    }
}

// ---------------- exact fp32 label logit ----------------
__global__ void zy_kernel(const float* __restrict__ x, const float* __restrict__ w,
                          const void* __restrict__ y) {
    int row  = blockIdx.x * 4 + (threadIdx.x >> 5);
    int lane = threadIdx.x & 31;
    if (row >= NROWS) return;
    int yv = load_label(y, row);
    int cls = (yv < 0) ? 0 : ((yv >= VDIM) ? 0 : yv);
    const float4* xr = reinterpret_cast<const float4*>(x + (size_t)row * KDIM);
    const float4* wr = reinterpret_cast<const float4*>(w + (size_t)cls * KDIM);
    float s = 0.f;
    #pragma unroll 4
    for (int i = lane; i < KDIM / 4; i += 32) {
        float4 a = xr[i], b = wr[i];
        s += a.x * b.x + a.y * b.y + a.z * b.z + a.w * b.w;
    }
    #pragma unroll
    for (int o = 16; o > 0; o >>= 1) s += __shfl_xor_sync(0xffffffffu, s, o);
    if (lane == 0) g_zy[row] = s;
}

// ---------------- PTX helpers ----------------
__device__ __forceinline__ void cp16(uint32_t dst, const void* src) {
    asm volatile("cp.async.cg.shared.global [%0], [%1], 16;\n" :: "r"(dst), "l"(src));
}
__device__ __forceinline__ void ldsm4(uint32_t* d, uint32_t addr) {
    asm volatile("ldmatrix.sync.aligned.m8n8.x4.shared.b16 {%0,%1,%2,%3}, [%4];"
        : "=r"(d[0]), "=r"(d[1]), "=r"(d[2]), "=r"(d[3]) : "r"(addr));
}
// fp8 e4m3 MMA, K=32: byte-layout-compatible with bf16 m16n8k16 fragments
__device__ __forceinline__ void mma16832(float* c, const uint32_t* a, uint32_t b0, uint32_t b1) {
    asm volatile("mma.sync.aligned.m16n8k32.row.col.f32.e4m3.e4m3.f32 "
        "{%0,%1,%2,%3}, {%4,%5,%6,%7}, {%8,%9}, {%0,%1,%2,%3};"
        : "+f"(c[0]), "+f"(c[1]), "+f"(c[2]), "+f"(c[3])
        : "r"(a[0]), "r"(a[1]), "r"(a[2]), "r"(a[3]), "r"(b0), "r"(b1));
}

// prefetch one K-stage: A (256 rows x 128B) + B (128 rows x 128B), 512 threads
__device__ __forceinline__ void prefetch_tile(const uint8_t* gA, const uint8_t* gB,
                                              uint32_t stage_base, int k0, int tid) {
    #pragma unroll
    for (int i = 0; i < 4; i++) {               // A: 256 rows x 8 chunks = 2048
        int g = tid + NTHREADS * i;
        int rr = g >> 3;
        int cc = g & 7;
        uint32_t off = rr * ROWB + cc * 16;
        cp16(stage_base + off, gA + (size_t)rr * KDIM + k0 + cc * 16);
    }
    #pragma unroll
    for (int i = 0; i < 2; i++) {               // B: 128 rows x 8 chunks = 1024
        int g = tid + NTHREADS * i;
        int rr = g >> 3;
        int cc = g & 7;
        uint32_t off = rr * ROWB + cc * 16;
        cp16(stage_base + ABYTES_A + off, gB + (size_t)rr * KDIM + k0 + cc * 16);
    }
    asm volatile("cp.async.commit_group;\n" ::: "memory");
}

// ---------------- fused fp8 GEMM + streaming sum-exp epilogue ----------------
__global__ void __launch_bounds__(NTHREADS) gemm_ce_kernel() {
    extern __shared__ __align__(16) char smem_raw[];

    const int tid  = threadIdx.x;
    const int lane = tid & 31;
    const int wid  = tid >> 5;
    const int wm   = wid >> 2;   // 0..3 (M dim of warp grid)
    const int wn   = wid & 3;    // 0..3 (N dim)
    const int bid  = blockIdx.x;
    const int vt   = bid >> 4;   // 16 consecutive bids share vtile -> L2 reuse of W band
    const int rt   = bid & 15;
    const int row0 = rt * BM;
    const int col0 = vt * BN;

    const uint8_t* gA = g_xb + (size_t)row0 * KDIM;
    const uint8_t* gB = g_wb + (size_t)col0 * KDIM;

    const uint32_t sbase = (uint32_t)__cvta_generic_to_shared(smem_raw);

    float acc[4][4][4];
    #pragma unroll
    for (int i = 0; i < 4; i++)
        #pragma unroll
        for (int j = 0; j < 4; j++)
            #pragma unroll
            for (int k = 0; k < 4; k++) acc[i][j][k] = 0.f;

    // prime stages 0..NSTAGE-2
    #pragma unroll
    for (int p = 0; p < NSTAGE - 1; p++)
        prefetch_tile(gA, gB, sbase + p * STAGE, p * BK, tid);

    const int row_in = lane & 15;
    const int khalf  = (lane >> 4) & 1;
    const uint32_t aoff = (wm * 64 + row_in) * ROWB + khalf * 16;
    const uint32_t boff = (wn * 32 + row_in) * ROWB + khalf * 16;

    int stage = 0;
    for (int kt = 0; kt < NK; kt++) {
        if (kt + NSTAGE - 1 < NK) {
            int ps = stage + NSTAGE - 1; if (ps >= NSTAGE) ps -= NSTAGE;
            prefetch_tile(gA, gB, sbase + ps * STAGE, (kt + NSTAGE - 1) * BK, tid);
            asm volatile("cp.async.wait_group %0;\n" :: "n"(NSTAGE - 1) : "memory");
        } else {
            int rem = NK - 1 - kt;
            if (rem >= 1) asm volatile("cp.async.wait_group 1;\n" ::: "memory");
            else          asm volatile("cp.async.wait_group 0;\n" ::: "memory");
        }
        __syncthreads();

        const uint32_t as = sbase + stage * STAGE;
        const uint32_t bs = as + ABYTES_A;
        #pragma unroll
        for (int ks = 0; ks < 4; ks++) {        // 4 x 32 fp8 = 128 K-elems
            uint32_t a[4][4], b[2][4];
            #pragma unroll
            for (int mt = 0; mt < 4; mt++)
                ldsm4(a[mt], as + aoff + mt * (16 * ROWB) + ks * 32);
            #pragma unroll
            for (int pp = 0; pp < 2; pp++)
                ldsm4(b[pp], bs + boff + pp * (16 * ROWB) + ks * 32);
            #pragma unroll
            for (int mt = 0; mt < 4; mt++) {
                mma16832(acc[mt][0], a[mt], b[0][0], b[0][2]);
                mma16832(acc[mt][1], a[mt], b[0][1], b[0][3]);
                mma16832(acc[mt][2], a[mt], b[1][0], b[1][2]);
                mma16832(acc[mt][3], a[mt], b[1][1], b[1][3]);
            }
        }
        __syncthreads();
        if (++stage >= NSTAGE) stage = 0;
    }

    // ----- epilogue: per-row sum(exp(z)) over this vtile -----
    float* rs = (float*)smem_raw;   // reuse smem: [4 warp_n][BM]

    #pragma unroll
    for (int mt = 0; mt < 4; mt++) {
        #pragma unroll
        for (int h = 0; h < 2; h++) {
            int lrow = wm * 64 + mt * 16 + (lane >> 2) + h * 8;
            float s = 0.f;
            #pragma unroll
            for (int nt = 0; nt < 4; nt++) {
                #pragma unroll
                for (int j = 0; j < 2; j++) {
                    int col = col0 + wn * 32 + nt * 8 + (lane & 3) * 2 + j;
                    float z = acc[mt][nt][h * 2 + j];
                    if (col < VDIM) s += fast_exp(z);
                }
            }
            s += __shfl_xor_sync(0xffffffffu, s, 1);
            s += __shfl_xor_sync(0xffffffffu, s, 2);
            if ((lane & 3) == 0) rs[wn * BM + lrow] = s;
        }
    }
    __syncthreads();
    if (tid < BM)
        g_spart[(size_t)vt * NROWS + row0 + tid] =
            rs[tid] + rs[BM + tid] + rs[2 * BM + tid] + rs[3 * BM + tid];
}

// ---------------- reduction across vtiles -> per-row NLL ----------------
__global__ void reduce_rows_kernel(const void* __restrict__ y) {
    int row  = blockIdx.x * 8 + (threadIdx.x >> 5);
    int lane = threadIdx.x & 31;
    if (row >= NROWS) return;
    float s = 0.f;
    for (int t = lane; t < VTILES; t += 32) s += g_spart[(size_t)t * NROWS + row];
    #pragma unroll
    for (int o = 16; o > 0; o >>= 1) s += __shfl_xor_sync(0xffffffffu, s, o);
    if (lane == 0) {
        int yv = load_label(y, row);
        bool valid = (yv != IGNORE_IDX);
        float nll = logf(s) - g_zy[row];
        g_nll[row] = valid ? nll : 0.f;
        g_vld[row] = valid ? 1.f : 0.f;
    }
}

// ---------------- deterministic final reduction ----------------
__global__ void finalize_kernel(float* __restrict__ out) {
    __shared__ float ss[256], sc[256];
    int t = threadIdx.x;
    float s = 0.f, c = 0.f;
    for (int i = t; i < NROWS; i += 256) { s += g_nll[i]; c += g_vld[i]; }
    ss[t] = s; sc[t] = c;
    __syncthreads();
    for (int o = 128; o > 0; o >>= 1) {
        if (t < o) { ss[t] += ss[t + o]; sc[t] += sc[t + o]; }
        __syncthreads();
    }
    if (t == 0) out[0] = ss[0] / fmaxf(sc[0], 1.f);
}

// ---------------- launcher ----------------
extern "C" void kernel_launch(void* const* d_in, const int* in_sizes, int n_in,
                              void* d_out, int out_size) {
    const float* x = (const float*)d_in[0];
    const float* w = (const float*)d_in[1];
    const void*  y = d_in[2];
    for (int i = 0; i < n_in; i++) {
        if (in_sizes[i] == NROWS)              y = d_in[i];
        else if (in_sizes[i] == NROWS * KDIM)  x = (const float*)d_in[i];
        else                                   w = (const float*)d_in[i];
    }

    cudaFuncSetAttribute(gemm_ce_kernel,
                         cudaFuncAttributeMaxDynamicSharedMemorySize, SMEM_REQ);

    detect_y_kernel<<<1, 256>>>((const int*)y);
    conv_w_kernel<<<4096, 256>>>(w);
    conv_x_kernel<<<2048, 256>>>(x);
    zy_kernel<<<NROWS / 4, 128>>>(x, w, y);
    gemm_ce_kernel<<<VTILES * (NROWS / BM), NTHREADS, SMEM_REQ>>>();
    reduce_rows_kernel<<<NROWS / 8, 256>>>(y);
    finalize_kernel<<<1, 256>>>((float*)d_out);
}